// round 17
// baseline (speedup 1.0000x reference)
#include <cuda_runtime.h>
#include <cuda_fp16.h>
#include <cstdint>

// ---------------------------------------------------------------------------
// Problem dims (fixed by the reference): E=1024, H=16, DQ=DV=64, B=8, S=4096
// ---------------------------------------------------------------------------
#define M_TOK 32768      // B*S tokens
#define K_E   1024       // embedding dim
#define N_QK  2048       // H*(DQ+DQ)

// ---------------------------------------------------------------------------
// Scratch (static __device__ — no runtime allocation allowed). All
// intermediates fp16 (consumers round to fp16 anyway or renormalize).
// ---------------------------------------------------------------------------
__device__ __half g_qkh[(size_t)M_TOK * N_QK];   // QKV gemm out / attn in
__device__ __half g_vh [(size_t)M_TOK * K_E];
__device__ __half g_aoh[(size_t)M_TOK * K_E];    // attn out / proj in
__device__ __half g_ph [(size_t)M_TOK * K_E];    // proj out / LN1 in
__device__ __half g_hh [(size_t)M_TOK * K_E];    // LN1 out / ff in
__device__ __half g_fh [(size_t)M_TOK * K_E];    // ff out / LN2 in
__device__ __half g_xh [(size_t)M_TOK * K_E];    // x in fp16 (gemm A + residual)
__device__ __half g_wqk[(size_t)N_QK * K_E];     // fp16 weights
__device__ __half g_wv [(size_t)K_E * K_E];
__device__ __half g_wp [(size_t)K_E * K_E];
__device__ __half g_wf [(size_t)K_E * K_E];

// ---------------------------------------------------------------------------
// PTX helpers (plain sm_103 target: no 'a'-features; legacy mma.sync path)
// ---------------------------------------------------------------------------
__device__ __forceinline__ uint32_t smem_u32(const void* p) {
    return (uint32_t)__cvta_generic_to_shared(p);
}
__device__ __forceinline__ void cp_async16(uint32_t dst, const void* src) {
    asm volatile("cp.async.cg.shared.global [%0], [%1], 16;\n" :: "r"(dst), "l"(src));
}
__device__ __forceinline__ void cp_commit() {
    asm volatile("cp.async.commit_group;\n");
}
template <int N>
__device__ __forceinline__ void cp_wait() {
    asm volatile("cp.async.wait_group %0;\n" :: "n"(N));
}
__device__ __forceinline__ void ldsm_x4(uint32_t* r, uint32_t a) {
    asm volatile("ldmatrix.sync.aligned.m8n8.x4.shared.b16 {%0,%1,%2,%3}, [%4];\n"
                 : "=r"(r[0]), "=r"(r[1]), "=r"(r[2]), "=r"(r[3]) : "r"(a));
}
__device__ __forceinline__ void mma_f16(float* d, const uint32_t* a, const uint32_t* b) {
    asm volatile("mma.sync.aligned.m16n8k16.row.col.f32.f16.f16.f32 "
                 "{%0,%1,%2,%3}, {%4,%5,%6,%7}, {%8,%9}, {%0,%1,%2,%3};\n"
                 : "+f"(d[0]), "+f"(d[1]), "+f"(d[2]), "+f"(d[3])
                 : "r"(a[0]), "r"(a[1]), "r"(a[2]), "r"(a[3]),
                   "r"(b[0]), "r"(b[1]));
}

// ---------------------------------------------------------------------------
// Converts: x (big) and all 4 weight matrices (one fused launch)
// ---------------------------------------------------------------------------
__global__ void __launch_bounds__(256) cvt_f2h(
    const float* __restrict__ in, __half* __restrict__ out, int n)
{
    int i = (blockIdx.x * 256 + threadIdx.x) << 3;
    if (i >= n) return;
    float4 a = *(const float4*)(in + i);
    float4 b = *(const float4*)(in + i + 4);
    __half2 h0 = __floats2half2_rn(a.x, a.y);
    __half2 h1 = __floats2half2_rn(a.z, a.w);
    __half2 h2 = __floats2half2_rn(b.x, b.y);
    __half2 h3 = __floats2half2_rn(b.z, b.w);
    uint4 u;
    u.x = *(uint32_t*)&h0; u.y = *(uint32_t*)&h1;
    u.z = *(uint32_t*)&h2; u.w = *(uint32_t*)&h3;
    *(uint4*)(out + i) = u;
}

__global__ void __launch_bounds__(256) cvt_weights(
    const float* __restrict__ qkw, const float* __restrict__ vw,
    const float* __restrict__ pw,  const float* __restrict__ fw,
    __half* __restrict__ wqk, __half* __restrict__ wv,
    __half* __restrict__ wp,  __half* __restrict__ wf)
{
    const size_t NW1 = (size_t)N_QK * K_E;   // 2097152
    const size_t NW2 = (size_t)K_E * K_E;    // 1048576
    size_t i = ((size_t)blockIdx.x * 256 + threadIdx.x) << 3;
    const float* src; __half* dst; size_t off;
    if (i < NW1)                 { src = qkw; dst = wqk; off = i; }
    else if (i < NW1 + NW2)      { src = vw;  dst = wv;  off = i - NW1; }
    else if (i < NW1 + 2 * NW2)  { src = pw;  dst = wp;  off = i - NW1 - NW2; }
    else                         { src = fw;  dst = wf;  off = i - NW1 - 2 * NW2; }
    float4 a = *(const float4*)(src + off);
    float4 b = *(const float4*)(src + off + 4);
    __half2 h0 = __floats2half2_rn(a.x, a.y);
    __half2 h1 = __floats2half2_rn(a.z, a.w);
    __half2 h2 = __floats2half2_rn(b.x, b.y);
    __half2 h3 = __floats2half2_rn(b.z, b.w);
    uint4 u;
    u.x = *(uint32_t*)&h0; u.y = *(uint32_t*)&h1;
    u.z = *(uint32_t*)&h2; u.w = *(uint32_t*)&h3;
    *(uint4*)(dst + off) = u;
}

// ---------------------------------------------------------------------------
// fp16 GEMM (R14 winner, unchanged): C[M,N] = A @ W^T + bias (opt exact GELU)
// BM=128, BN=128, BK=64 halves. 128 threads = 4 warps (2x2), warp tile 64x64.
// 2 CTAs/SM, 3-stage cp.async pipeline, fragment double buffering.
// ---------------------------------------------------------------------------
#define STAGE_F 8192                 // uint32 per stage: 4096 A + 4096 B
#define GSMEM   (3 * STAGE_F * 4)    // 98304 bytes

__device__ __forceinline__ void gemm_load_tiles(
    float* as, const __half* Ag, const __half* Wg, int K, int lr, int lc)
{
    float* bs = as + 4096;
#pragma unroll
    for (int i = 0; i < 8; ++i) {            // A: 128 rows, 16 rows/pass
        int row = lr + (i << 4);
        int sw  = ((lc ^ (row & 7)) << 2);
        cp_async16(smem_u32(as + row * 32 + sw), Ag + (size_t)row * K + (lc << 3));
    }
#pragma unroll
    for (int i = 0; i < 8; ++i) {            // B: 128 rows
        int row = lr + (i << 4);
        int sw  = ((lc ^ (row & 7)) << 2);
        cp_async16(smem_u32(bs + row * 32 + sw), Wg + (size_t)row * K + (lc << 3));
    }
}

__device__ __forceinline__ void load_frags(
    uint32_t af[4][4], uint32_t bf[8][2], const float* as, int ks,
    int wm, int wn, int ro, int co)
{
    const float* bs = as + 4096;
    const int cg = (ks << 1) + co;
#pragma unroll
    for (int mi = 0; mi < 4; ++mi) {
        int row = wm + (mi << 4) + ro;
        ldsm_x4(af[mi], smem_u32(as + row * 32 + ((cg ^ (row & 7)) << 2)));
    }
#pragma unroll
    for (int jj = 0; jj < 4; ++jj) {
        int n = wn + (jj << 4) + ro;
        uint32_t t[4];
        ldsm_x4(t, smem_u32(bs + n * 32 + ((cg ^ (n & 7)) << 2)));
        bf[jj * 2    ][0] = t[0]; bf[jj * 2    ][1] = t[2];   // n0-7
        bf[jj * 2 + 1][0] = t[1]; bf[jj * 2 + 1][1] = t[3];   // n8-15
    }
}

__device__ __forceinline__ void mma_all(
    float acc[4][8][4], uint32_t af[4][4], uint32_t bf[8][2])
{
#pragma unroll
    for (int mi = 0; mi < 4; ++mi)
#pragma unroll
        for (int nj = 0; nj < 8; ++nj)
            mma_f16(acc[mi][nj], af[mi], bf[nj]);
}

template <bool GELU, bool HALF_OUT>
__global__ void __launch_bounds__(128, 2) gemm_f16(
    const __half* __restrict__ A, const __half* __restrict__ W,
    const float* __restrict__ bias, void* __restrict__ C,
    int M, int N, int K)
{
    extern __shared__ float smem[];   // 3 stages x 8192 uint32 = 96 KB

    const int tid  = threadIdx.x;
    const int lane = tid & 31;
    const int warp = tid >> 5;
    const int bm = blockIdx.y << 7;
    const int bn = blockIdx.x << 7;
    const int wm = (warp & 1) << 6;
    const int wn = (warp >> 1) << 6;

    const int lr = tid >> 3;
    const int lc = tid & 7;
    const int KT = K >> 6;

    const int ro = (((lane >> 3) & 1) << 3) + (lane & 7);
    const int co = lane >> 4;

    float acc[4][8][4];
#pragma unroll
    for (int i = 0; i < 4; ++i)
#pragma unroll
        for (int j = 0; j < 8; ++j) {
            acc[i][j][0] = 0.f; acc[i][j][1] = 0.f;
            acc[i][j][2] = 0.f; acc[i][j][3] = 0.f;
        }

    const __half* Abase = A + (size_t)bm * K;
    const __half* Wbase = W + (size_t)bn * K;

#pragma unroll
    for (int p = 0; p < 2; ++p) {
        gemm_load_tiles(smem + p * STAGE_F, Abase + (p << 6), Wbase + (p << 6),
                        K, lr, lc);
        cp_commit();
    }
    cp_wait<1>();
    __syncthreads();

    uint32_t af[2][4][4], bf[2][8][2];
    load_frags(af[0], bf[0], smem, 0, wm, wn, ro, co);
    int cur = 0;

    int s_cur = 0;
    for (int kt = 0; kt < KT; ++kt) {
        const float* as = smem + s_cur * STAGE_F;
        const int s_nxt = (s_cur + 1 == 3) ? 0 : s_cur + 1;
        const int s_fre = s_cur ? s_cur - 1 : 2;

#pragma unroll
        for (int ks = 0; ks < 3; ++ks) {
            load_frags(af[cur ^ 1], bf[cur ^ 1], as, ks + 1, wm, wn, ro, co);
            mma_all(acc, af[cur], bf[cur]);
            cur ^= 1;
        }

        if (kt + 1 < KT) {
            if (kt + 2 < KT)
                gemm_load_tiles(smem + s_fre * STAGE_F,
                                Abase + ((size_t)(kt + 2) << 6),
                                Wbase + ((size_t)(kt + 2) << 6),
                                K, lr, lc);
            cp_commit();
            cp_wait<1>();
            __syncthreads();
            load_frags(af[cur ^ 1], bf[cur ^ 1],
                       smem + s_nxt * STAGE_F, 0, wm, wn, ro, co);
        }
        mma_all(acc, af[cur], bf[cur]);    // ks = 3
        cur ^= 1;
        s_cur = s_nxt;
    }

    // epilogue: bias (+gelu), stores fp16 or fp32
    const int g  = lane >> 2;
    const int tg = lane & 3;
#pragma unroll
    for (int mi = 0; mi < 4; ++mi) {
        int r0 = bm + wm + (mi << 4) + g;
#pragma unroll
        for (int nj = 0; nj < 8; ++nj) {
            int col = bn + wn + (nj << 3) + (tg << 1);
            float b0 = bias[col], b1 = bias[col + 1];
            float v0 = acc[mi][nj][0] + b0;
            float v1 = acc[mi][nj][1] + b1;
            float v2 = acc[mi][nj][2] + b0;
            float v3 = acc[mi][nj][3] + b1;
            if (GELU) {
                v0 *= normcdff(v0);
                v1 *= normcdff(v1);
                v2 *= normcdff(v2);
                v3 *= normcdff(v3);
            }
            if (HALF_OUT) {
                __half* Ch = (__half*)C;
                *(__half2*)(Ch + (size_t)r0 * N + col)       = __floats2half2_rn(v0, v1);
                *(__half2*)(Ch + (size_t)(r0 + 8) * N + col) = __floats2half2_rn(v2, v3);
            } else {
                float* Cf = (float*)C;
                *(float2*)(Cf + (size_t)r0 * N + col)       = make_float2(v0, v1);
                *(float2*)(Cf + (size_t)(r0 + 8) * N + col) = make_float2(v2, v3);
            }
        }
    }
}

// ---------------------------------------------------------------------------
// Per-token head attention, now TWO tokens per CTA (256 threads): halves the
// block count (32768 -> 16384) to amortize scheduling/launch latency.
// fp16 in -> fp32 smem compute (conflict-free padded layout) -> fp16 out.
// ---------------------------------------------------------------------------
#define KSTR 68    // padded k-row stride (floats)
#define ASTR 17    // padded attn-row stride (floats)

__device__ __forceinline__ void unpack8(const uint4 u, float* dst) {
    float2 f0 = __half22float2(*(__half2*)&u.x);
    float2 f1 = __half22float2(*(__half2*)&u.y);
    float2 f2 = __half22float2(*(__half2*)&u.z);
    float2 f3 = __half22float2(*(__half2*)&u.w);
    dst[0] = f0.x; dst[1] = f0.y; dst[2] = f1.x; dst[3] = f1.y;
    dst[4] = f2.x; dst[5] = f2.y; dst[6] = f3.x; dst[7] = f3.y;
}

__global__ void __launch_bounds__(256) attn_kernel(
    const __half* __restrict__ QK, const __half* __restrict__ V,
    __half* __restrict__ O)
{
    const int tid  = threadIdx.x;
    const int half = tid >> 7;          // which token of the pair
    const int ht   = tid & 127;
    const int t    = blockIdx.x * 2 + half;
    __shared__ float qs[2][1024], ks2[2][15 * KSTR + 64 + 4],
                     vs[2][1024], at[2][16 * ASTR];

    const uint4* qk8 = (const uint4*)(QK + (size_t)t * 2048);  // 256 x 8 halves
    const uint4* v8  = (const uint4*)(V  + (size_t)t * 1024);  // 128 x 8 halves

    {
        unpack8(qk8[ht], qs[half] + ht * 8);
        int kg = ht >> 3, col = (ht & 7) << 3;
        unpack8(qk8[128 + ht], ks2[half] + kg * KSTR + col);
        unpack8(v8[ht], vs[half] + ht * 8);
    }
    __syncthreads();

#pragma unroll
    for (int sidx = ht; sidx < 256; sidx += 128) {
        int h = sidx >> 4, gg = sidx & 15;
        const float4* qp = (const float4*)(qs[half]  + h  * 64);
        const float4* kp = (const float4*)(ks2[half] + gg * KSTR);
        float a = 0.f;
#pragma unroll
        for (int d = 0; d < 16; ++d) {
            float4 x = qp[d], y = kp[d];
            a += x.x * y.x + x.y * y.y + x.z * y.z + x.w * y.w;
        }
        at[half][h * ASTR + gg] = a * 0.125f;
    }
    __syncthreads();

    if (ht < 16) {
        float m = -1e30f;
#pragma unroll
        for (int gg = 0; gg < 16; ++gg) m = fmaxf(m, at[half][ht * ASTR + gg]);
        float s = 0.f;
#pragma unroll
        for (int gg = 0; gg < 16; ++gg) {
            float e = expf(at[half][ht * ASTR + gg] - m);
            at[half][ht * ASTR + gg] = e;
            s += e;
        }
        float inv = 1.f / s;
#pragma unroll
        for (int gg = 0; gg < 16; ++gg) at[half][ht * ASTR + gg] *= inv;
    }
    __syncthreads();

    __half2* out = (__half2*)(O + (size_t)t * 1024);
#pragma unroll
    for (int oo = ht; oo < 512; oo += 128) {
        int o = oo << 1;
        int h = o >> 6, d = o & 63;
        float a0 = 0.f, a1 = 0.f;
#pragma unroll
        for (int gg = 0; gg < 16; ++gg) {
            float w = at[half][h * ASTR + gg];
            a0 += w * vs[half][gg * 64 + d];
            a1 += w * vs[half][gg * 64 + d + 1];
        }
        out[oo] = __floats2half2_rn(a0, a1);
    }
}

// ---------------------------------------------------------------------------
// LayerNorm of (P + X) over last dim 1024; P and X fp16, fp32 internals.
// One warp per token. HALF_OUT writes fp16; else fp32 (final output).
// ---------------------------------------------------------------------------
template <bool HALF_OUT>
__global__ void __launch_bounds__(256) ln_kernel(
    const __half* __restrict__ P, const __half* __restrict__ X,
    const float* __restrict__ gw, const float* __restrict__ bw,
    void* __restrict__ Optr)
{
    const int t    = blockIdx.x * 8 + (threadIdx.x >> 5);
    const int lane = threadIdx.x & 31;
    const uint2* p4 = (const uint2*)(P + (size_t)t * 1024);
    const uint2* x4 = (const uint2*)(X + (size_t)t * 1024);

    float4 v[8];
    float s = 0.f;
#pragma unroll
    for (int j = 0; j < 8; ++j) {
        int i = lane + (j << 5);
        uint2 ua = p4[i], uc = x4[i];
        float2 a0 = __half22float2(*(__half2*)&ua.x);
        float2 a1 = __half22float2(*(__half2*)&ua.y);
        float2 c0 = __half22float2(*(__half2*)&uc.x);
        float2 c1 = __half22float2(*(__half2*)&uc.y);
        v[j].x = a0.x + c0.x; v[j].y = a0.y + c0.y;
        v[j].z = a1.x + c1.x; v[j].w = a1.y + c1.y;
        s += v[j].x + v[j].y + v[j].z + v[j].w;
    }
#pragma unroll
    for (int o = 16; o > 0; o >>= 1) s += __shfl_xor_sync(0xffffffffu, s, o);
    const float mu = s * (1.0f / 1024.0f);

    float q = 0.f;
#pragma unroll
    for (int j = 0; j < 8; ++j) {
        float dx;
        dx = v[j].x - mu; q += dx * dx;
        dx = v[j].y - mu; q += dx * dx;
        dx = v[j].z - mu; q += dx * dx;
        dx = v[j].w - mu; q += dx * dx;
    }
#pragma unroll
    for (int o = 16; o > 0; o >>= 1) q += __shfl_xor_sync(0xffffffffu, q, o);
    const float r = rsqrtf(q * (1.0f / 1024.0f) + 1e-5f);

    const float4* g4 = (const float4*)gw;
    const float4* b4 = (const float4*)bw;
#pragma unroll
    for (int j = 0; j < 8; ++j) {
        int i = lane + (j << 5);
        float4 gg = g4[i], bb = b4[i], ov;
        ov.x = (v[j].x - mu) * r * gg.x + bb.x;
        ov.y = (v[j].y - mu) * r * gg.y + bb.y;
        ov.z = (v[j].z - mu) * r * gg.z + bb.z;
        ov.w = (v[j].w - mu) * r * gg.w + bb.w;
        if (HALF_OUT) {
            __half2 h0 = __floats2half2_rn(ov.x, ov.y);
            __half2 h1 = __floats2half2_rn(ov.z, ov.w);
            uint2 u;
            u.x = *(uint32_t*)&h0; u.y = *(uint32_t*)&h1;
            *(uint2*)((__half*)Optr + (size_t)t * 1024 + (i << 2)) = u;
        } else {
            *(float4*)((float*)Optr + (size_t)t * 1024 + (i << 2)) = ov;
        }
    }
}

// ---------------------------------------------------------------------------
// Launch.  Order matters for ncu (captures launch index 3 = v-gemm):
//   0 cvt_f2h(x)  1 cvt_weights  2 qk-gemm  3 v-gemm  4 attn  5 proj ...
// ---------------------------------------------------------------------------
extern "C" void kernel_launch(void* const* d_in, const int* in_sizes, int n_in,
                              void* d_out, int out_size)
{
    const float* x      = (const float*)d_in[0];
    const float* qk_w   = (const float*)d_in[1];
    const float* qk_b   = (const float*)d_in[2];
    const float* v_w    = (const float*)d_in[3];
    const float* v_b    = (const float*)d_in[4];
    const float* proj_w = (const float*)d_in[5];
    const float* proj_b = (const float*)d_in[6];
    const float* ff_w   = (const float*)d_in[7];
    const float* ff_b   = (const float*)d_in[8];
    const float* ln_g   = (const float*)d_in[9];
    const float* ln_b   = (const float*)d_in[10];
    float* out = (float*)d_out;
    (void)in_sizes; (void)n_in; (void)out_size;

    cudaFuncSetAttribute((const void*)gemm_f16<false, true>,
                         cudaFuncAttributeMaxDynamicSharedMemorySize, GSMEM);
    cudaFuncSetAttribute((const void*)gemm_f16<true, true>,
                         cudaFuncAttributeMaxDynamicSharedMemorySize, GSMEM);

    __half *qkh, *vh, *aoh, *ph, *hh, *fh, *xh, *wqk, *wv, *wp, *wf;
    cudaGetSymbolAddress((void**)&qkh, g_qkh);
    cudaGetSymbolAddress((void**)&vh,  g_vh);
    cudaGetSymbolAddress((void**)&aoh, g_aoh);
    cudaGetSymbolAddress((void**)&ph,  g_ph);
    cudaGetSymbolAddress((void**)&hh,  g_hh);
    cudaGetSymbolAddress((void**)&fh,  g_fh);
    cudaGetSymbolAddress((void**)&xh,  g_xh);
    cudaGetSymbolAddress((void**)&wqk, g_wqk);
    cudaGetSymbolAddress((void**)&wv,  g_wv);
    cudaGetSymbolAddress((void**)&wp,  g_wp);
    cudaGetSymbolAddress((void**)&wf,  g_wf);

    const dim3 blk(128);
    const int NX = M_TOK * K_E;        // 33.5M
    const int NWALL = (N_QK + 3 * K_E) * K_E;   // 5.24M weight elems

    // 0-1: converts
    cvt_f2h<<<NX / 2048, 256>>>(x, xh, NX);
    cvt_weights<<<NWALL / 2048, 256>>>(qk_w, v_w, proj_w, ff_w, wqk, wv, wp, wf);

    // 2-3: QKV projections (fp16 out); idx 3 = canonical N=1024 GEMM for ncu
    gemm_f16<false, true><<<dim3(N_QK / 128, M_TOK / 128), blk, GSMEM>>>(
        xh, wqk, qk_b, qkh, M_TOK, N_QK, K_E);
    gemm_f16<false, true><<<dim3(K_E / 128, M_TOK / 128), blk, GSMEM>>>(
        xh, wv, v_b, vh, M_TOK, K_E, K_E);

    // 4: per-token head attention (2 tokens per CTA)
    attn_kernel<<<M_TOK / 2, 256>>>(qkh, vh, aoh);

    // 5: output projection (fp16 out)
    gemm_f16<false, true><<<dim3(K_E / 128, M_TOK / 128), blk, GSMEM>>>(
        aoh, wp, proj_b, ph, M_TOK, K_E, K_E);

    // 6: h = LN(p + x)  (fp16 out)
    ln_kernel<true><<<M_TOK / 8, 256>>>(ph, xh, ln_g, ln_b, hh);

    // 7: f = gelu(h @ ff_w^T + ff_b)  (fp16 out)
    gemm_f16<true, true><<<dim3(K_E / 128, M_TOK / 128), blk, GSMEM>>>(
        hh, wf, ff_b, fh, M_TOK, K_E, K_E);

    // 8: out = LN(f + x)  (fp32 out)
    ln_kernel<false><<<M_TOK / 8, 256>>>(fh, xh, ln_g, ln_b, out);
}